// round 13
// baseline (speedup 1.0000x reference)
#include <cuda_runtime.h>
#include <cuda_fp16.h>
#include <cstdint>

#define B_ 2
#define S_ 4096
#define E_ 1024
#define H_ 16
#define D_ 64
#define NTOK (B_*S_)
#define NELEM (NTOK*E_)
#define KAUG 1088   // 1024 + 64 (bias row + zero pad) = 17 tiles of BK=64
#define LOG2E 1.4426950408889634f
#define NPERSIST 304   // 2 blocks x 152 SMs (GB300)

__device__ __half g_q[NELEM];
__device__ __half g_k[NELEM];
__device__ __half g_v[NELEM];
__device__ __half g_xh[NTOK * KAUG];       // fp16 X, augmented
__device__ __half g_wh[3 * E_ * KAUG];     // fp16 W (scaled), bias folded

__device__ __forceinline__ void cp16(unsigned int dst, const void* src) {
    asm volatile("cp.async.cg.shared.global [%0], [%1], 16;" :: "r"(dst), "l"(src));
}
__device__ __forceinline__ unsigned int sptr(const void* p) {
    return (unsigned int)__cvta_generic_to_shared(p);
}
__device__ __forceinline__ unsigned hexp2pk(float a, float b) {
    __half2 hv = __floats2half2_rn(a, b);
    unsigned r;
    asm("ex2.approx.f16x2 %0, %1;" : "=r"(r) : "r"(*(unsigned*)&hv));
    return r;
}
__device__ __forceinline__ void mma16816(float* d, const unsigned* a, const unsigned* b) {
    asm volatile("mma.sync.aligned.m16n8k16.row.col.f32.f16.f16.f32 "
                 "{%0,%1,%2,%3}, {%4,%5,%6,%7}, {%8,%9}, {%0,%1,%2,%3};"
                 : "+f"(d[0]), "+f"(d[1]), "+f"(d[2]), "+f"(d[3])
                 : "r"(a[0]), "r"(a[1]), "r"(a[2]), "r"(a[3]), "r"(b[0]), "r"(b[1]));
}
__device__ __forceinline__ void ldsm4(unsigned* r, unsigned addr) {
    asm volatile("ldmatrix.sync.aligned.m8n8.x4.shared.b16 {%0,%1,%2,%3}, [%4];"
                 : "=r"(r[0]), "=r"(r[1]), "=r"(r[2]), "=r"(r[3]) : "r"(addr));
}
__device__ __forceinline__ void ldsm4t(unsigned* r, unsigned addr) {
    asm volatile("ldmatrix.sync.aligned.m8n8.x4.trans.shared.b16 {%0,%1,%2,%3}, [%4];"
                 : "=r"(r[0]), "=r"(r[1]), "=r"(r[2]), "=r"(r[3]) : "r"(addr));
}

// ---------------------------------------------------------------------------
// One-time conversions fp32 -> fp16 with K-augmentation (8 elems / thread).
// ---------------------------------------------------------------------------
__global__ void __launch_bounds__(256) cvt_x(const float* __restrict__ X) {
    int idx8 = blockIdx.x * 256 + threadIdx.x;
    if (idx8 >= NTOK * (KAUG / 8)) return;
    int row = idx8 / (KAUG / 8);
    int c = (idx8 - row * (KAUG / 8)) * 8;
    __half2 h[4];
    if (c < 1024) {
        const float4* src = (const float4*)(X + (size_t)row * 1024 + c);
        float4 v0 = src[0], v1 = src[1];
        h[0] = __floats2half2_rn(v0.x, v0.y);
        h[1] = __floats2half2_rn(v0.z, v0.w);
        h[2] = __floats2half2_rn(v1.x, v1.y);
        h[3] = __floats2half2_rn(v1.z, v1.w);
    } else {
        h[0] = __floats2half2_rn(c == 1024 ? 1.0f : 0.0f, 0.0f);   // bias row
        h[1] = h[2] = h[3] = __floats2half2_rn(0.0f, 0.0f);
    }
    *(uint4*)(g_xh + (size_t)row * KAUG + c) = *(uint4*)h;
}

__global__ void __launch_bounds__(256) cvt_w(const float* __restrict__ qw, const float* __restrict__ qb,
                                             const float* __restrict__ kw, const float* __restrict__ kb,
                                             const float* __restrict__ vw, const float* __restrict__ vb) {
    const int which = blockIdx.y;
    const float* w = (which == 0) ? qw : ((which == 1) ? kw : vw);
    const float* b = (which == 0) ? qb : ((which == 1) ? kb : vb);
    const float scale = (which == 0) ? 0.125f * LOG2E : 1.0f;   // log2e folded into Q

    int idx8 = blockIdx.x * 256 + threadIdx.x;
    if (idx8 >= E_ * (KAUG / 8)) return;
    int n = idx8 / (KAUG / 8);
    int c = (idx8 - n * (KAUG / 8)) * 8;
    __half2 h[4];
    if (c < 1024) {
        const float4* src = (const float4*)(w + (size_t)n * 1024 + c);
        float4 v0 = src[0], v1 = src[1];
        h[0] = __floats2half2_rn(v0.x * scale, v0.y * scale);
        h[1] = __floats2half2_rn(v0.z * scale, v0.w * scale);
        h[2] = __floats2half2_rn(v1.x * scale, v1.y * scale);
        h[3] = __floats2half2_rn(v1.z * scale, v1.w * scale);
    } else {
        h[0] = __floats2half2_rn(c == 1024 ? b[n] * scale : 0.0f, 0.0f);
        h[1] = h[2] = h[3] = __floats2half2_rn(0.0f, 0.0f);
    }
    *(uint4*)(g_wh + (size_t)which * E_ * KAUG + (size_t)n * KAUG + c) = *(uint4*)h;
}

// ---------------------------------------------------------------------------
// Persistent projection GEMM (v3 pipeline + grid-stride over 1536 tiles).
// BM=128, BN=128, BK=64, 8 warps of 64x32, 2-stage cp.async, 2 blocks/SM.
// ---------------------------------------------------------------------------
#define GAP2 72
#define GSTG (128 * GAP2 * 2)
#define GEMM_SMEM (4 * GSTG)
#define GTILES (3 * 64 * 8)

__global__ void __launch_bounds__(256, 2) gemm_qkv() {
    extern __shared__ char smg[];

    const int tid = threadIdx.x;
    const int warp = tid >> 5;
    const int lane = tid & 31;
    const int wm = warp >> 2;
    const int wn = warp & 3;

    const int arbase = wm * 64 + (lane & 7) + ((lane & 8) ? 8 : 0);
    const int acolb = (lane & 16) ? 8 : 0;
    const int brbase = wn * 32 + ((lane & 16) ? 8 : 0) + (lane & 7);
    const int bcolb = (lane & 8) ? 8 : 0;
    const int r0 = lane >> 2;
    const int c0 = (lane & 3) * 2;

    for (int t = blockIdx.x; t < GTILES; t += gridDim.x) {
        const int which = t >> 9;
        const int rem = t & 511;
        const int m0 = (rem >> 3) << 7;
        const int n0 = (rem & 7) << 7;
        const __half* wbase = g_wh + (size_t)which * E_ * KAUG;
        __half* C = (which == 0) ? g_q : ((which == 1) ? g_k : g_v);

        float acc[4][4][4];
#pragma unroll
        for (int mi = 0; mi < 4; mi++)
#pragma unroll
            for (int nj = 0; nj < 4; nj++)
#pragma unroll
                for (int e = 0; e < 4; e++) acc[mi][nj][e] = 0.f;

        auto issue = [&](int kt, int s) {
            __half* Ad = (__half*)(smg + s * GSTG);
            __half* Bd = (__half*)(smg + 2 * GSTG + s * GSTG);
#pragma unroll
            for (int i = 0; i < 4; i++) {
                int c = tid + i * 256;
                int row = c >> 3, kc = (c & 7) * 8;
                cp16(sptr(&Ad[row * GAP2 + kc]), g_xh + (size_t)(m0 + row) * KAUG + kt * 64 + kc);
                cp16(sptr(&Bd[row * GAP2 + kc]), wbase + (size_t)(n0 + row) * KAUG + kt * 64 + kc);
            }
            asm volatile("cp.async.commit_group;" ::);
        };

        issue(0, 0);
        for (int kt = 0; kt < 17; kt++) {
            const int s = kt & 1;
            if (kt + 1 < 17) {
                issue(kt + 1, s ^ 1);
                asm volatile("cp.async.wait_group 1;" ::);
            } else {
                asm volatile("cp.async.wait_group 0;" ::);
            }
            __syncthreads();

            const __half* As = (const __half*)(smg + s * GSTG);
            const __half* Bsm = (const __half*)(smg + 2 * GSTG + s * GSTG);

#pragma unroll
            for (int tt = 0; tt < 4; tt++) {
                unsigned af[4][4];
#pragma unroll
                for (int mi = 0; mi < 4; mi++)
                    ldsm4(af[mi], sptr(&As[(arbase + mi * 16) * GAP2 + tt * 16 + acolb]));
                unsigned bf[2][4];
#pragma unroll
                for (int p = 0; p < 2; p++)
                    ldsm4(bf[p], sptr(&Bsm[(brbase + p * 16) * GAP2 + tt * 16 + bcolb]));
#pragma unroll
                for (int mi = 0; mi < 4; mi++) {
#pragma unroll
                    for (int p = 0; p < 2; p++) {
                        mma16816(acc[mi][2 * p],     af[mi], bf[p]);
                        mma16816(acc[mi][2 * p + 1], af[mi], bf[p] + 2);
                    }
                }
            }
            __syncthreads();
        }

        // Epilogue: direct half2 stores from accumulator fragments.
#pragma unroll
        for (int mi = 0; mi < 4; mi++) {
            const int row0 = m0 + wm * 64 + mi * 16 + r0;
#pragma unroll
            for (int nj = 0; nj < 4; nj++) {
                const int col = n0 + wn * 32 + nj * 8 + c0;
                __half2 h0 = __floats2half2_rn(acc[mi][nj][0], acc[mi][nj][1]);
                __half2 h1 = __floats2half2_rn(acc[mi][nj][2], acc[mi][nj][3]);
                *(__half2*)(C + (size_t)row0 * 1024 + col) = h0;
                *(__half2*)(C + (size_t)(row0 + 8) * 1024 + col) = h1;
            }
        }
    }
}

// ---------------------------------------------------------------------------
// Persistent banded attention: grid-stride over 1024 (b,h,chunk) tiles.
// Raw mma + ldmatrix, register softmax (log2 domain, ex2.approx.f16x2),
// double-buffered K/V, all-in-band fast path for interior subtiles.
// ---------------------------------------------------------------------------
#define AP 72
#define QS_OFF 0
#define KS_OFF (128*AP*2)
#define VS_OFF (KS_OFF + 2*64*AP*2)
#define FML_OFF (VS_OFF + 2*64*AP*2)
#define ATTN_SMEM (FML_OFF + 2*64*4)
#define ATILES (32 * 16 * 2)

__global__ void __launch_bounds__(256, 2) attn_mma(const int* __restrict__ am,
                                                   float* __restrict__ out) {
    extern __shared__ char smb[];
    __half* Qs = (__half*)(smb + QS_OFF);
    float* fml = (float*)(smb + FML_OFF);

    const int tid = threadIdx.x;
    const int lane = tid & 31;
    const int warp = tid >> 5;
    const int q0 = warp * 16;
    const int col0 = (lane & 3) * 2;

    for (int t = blockIdx.x; t < ATILES; t += gridDim.x) {
        const int chunk0 = (t & 31) * 128;
        const int h = (t >> 5) & 15;
        const int b = t >> 9;
        const size_t base = (size_t)b * S_ * E_ + h * 64;

#pragma unroll
        for (int r = 0; r < 4; r++) {
            int c = tid + r * 256;
            int row = c >> 3, off = (c & 7) * 8;
            *(uint4*)(&Qs[row * AP + off]) =
                *(const uint4*)(g_q + base + (size_t)(chunk0 + row) * E_ + off);
        }

        const int kt_start = (chunk0 >= 256) ? 0 : ((256 - chunk0) / 64);
        const int kt_end = min(10, (S_ + 192 - chunk0) / 64 + 1);

        auto issueKV = [&](int kt, int s) {
            const int kglob = chunk0 - 256 + kt * 64;
            __half* Kd = (__half*)(smb + KS_OFF + s * (64 * AP * 2));
            __half* Vd = (__half*)(smb + VS_OFF + s * (64 * AP * 2));
#pragma unroll
            for (int i = 0; i < 2; i++) {
                int c = tid + i * 256;
                int row = c >> 3, off = (c & 7) * 8;
                size_t g = base + (size_t)(kglob + row) * E_ + off;
                cp16(sptr(&Kd[row * AP + off]), g_k + g);
                cp16(sptr(&Vd[row * AP + off]), g_v + g);
            }
            asm volatile("cp.async.commit_group;" ::);
            if (tid < 64)
                fml[s * 64 + tid] =
                    (am[(size_t)b * S_ + kglob + tid] != 0) ? (-10000.f * LOG2E) : 0.f;
        };

        issueKV(kt_start, 0);
        __syncthreads();   // Qs + stage0 fml visible

        unsigned qa[4][4];
        {
            int qrow = q0 + (lane & 7) + ((lane & 8) ? 8 : 0);
            int qc = (lane & 16) ? 8 : 0;
#pragma unroll
            for (int tq = 0; tq < 4; tq++)
                ldsm4(qa[tq], sptr(&Qs[qrow * AP + tq * 16 + qc]));
        }

        float oacc[8][4];
#pragma unroll
        for (int j = 0; j < 8; j++)
#pragma unroll
            for (int e = 0; e < 4; e++) oacc[j][e] = 0.f;
        float lsum0 = 0.f, lsum1 = 0.f;
        const int rq0 = chunk0 + q0 + (lane >> 2);

        for (int kt = kt_start; kt < kt_end; kt++) {
            const int s = (kt - kt_start) & 1;
            const int kglob = chunk0 - 256 + kt * 64;
            if (kt + 1 < kt_end) {
                issueKV(kt + 1, s ^ 1);
                asm volatile("cp.async.wait_group 1;" ::);
            } else {
                asm volatile("cp.async.wait_group 0;" ::);
            }
            __syncthreads();
            const __half* Ks = (const __half*)(smb + KS_OFF + s * (64 * AP * 2));
            const __half* Vs = (const __half*)(smb + VS_OFF + s * (64 * AP * 2));
            const float* fm = fml + s * 64;

#pragma unroll
            for (int sub = 0; sub < 2; sub++) {
                const int klocal = sub * 32;
                const int d0 = kglob + klocal - (chunk0 + q0);   // key0 - qrow_base
                if (d0 > 256 + 15 || d0 + 31 < -256) continue;    // fully out of band

                float sacc[4][4];
#pragma unroll
                for (int j = 0; j < 4; j++)
#pragma unroll
                    for (int e = 0; e < 4; e++) sacc[j][e] = 0.f;
#pragma unroll
                for (int tq = 0; tq < 4; tq++) {
#pragma unroll
                    for (int p = 0; p < 2; p++) {
                        unsigned kb[4];
                        int krow = klocal + p * 16 + ((lane & 16) ? 8 : 0) + (lane & 7);
                        int kcol = tq * 16 + ((lane & 8) ? 8 : 0);
                        ldsm4(kb, sptr(&Ks[krow * AP + kcol]));
                        mma16816(sacc[2 * p], qa[tq], kb);
                        mma16816(sacc[2 * p + 1], qa[tq], kb + 2);
                    }
                }

                unsigned pa[2][4];
                if (d0 >= -241 && d0 <= 225) {
                    // fast path: every (row,key) in this warp subtile is in band
#pragma unroll
                    for (int jj = 0; jj < 4; jj++) {
                        const float f0 = fm[klocal + jj * 8 + col0];
                        const float f1 = fm[klocal + jj * 8 + col0 + 1];
                        unsigned p0 = hexp2pk(sacc[jj][0] + f0, sacc[jj][1] + f1);
                        unsigned p1 = hexp2pk(sacc[jj][2] + f0, sacc[jj][3] + f1);
                        float2 f0v = __half22float2(*(__half2*)&p0);
                        float2 f1v = __half22float2(*(__half2*)&p1);
                        lsum0 += f0v.x + f0v.y;
                        lsum1 += f1v.x + f1v.y;
                        pa[jj >> 1][(jj & 1) * 2 + 0] = p0;
                        pa[jj >> 1][(jj & 1) * 2 + 1] = p1;
                    }
                } else {
#pragma unroll
                    for (int jj = 0; jj < 4; jj++) {
                        const int keyg = kglob + klocal + jj * 8 + col0;
                        const float f0 = fm[klocal + jj * 8 + col0];
                        const float f1 = fm[klocal + jj * 8 + col0 + 1];
                        const int r00 = keyg - rq0;
                        const float t00 = (r00 >= -256 && r00 <= 256) ? sacc[jj][0] + f0 : -1e5f;
                        const float t01 = (r00 + 1 >= -256 && r00 + 1 <= 256) ? sacc[jj][1] + f1 : -1e5f;
                        const float t10 = (r00 - 8 >= -256 && r00 - 8 <= 256) ? sacc[jj][2] + f0 : -1e5f;
                        const float t11 = (r00 - 7 >= -256 && r00 - 7 <= 256) ? sacc[jj][3] + f1 : -1e5f;
                        unsigned p0 = hexp2pk(t00, t01);
                        unsigned p1 = hexp2pk(t10, t11);
                        float2 f0v = __half22float2(*(__half2*)&p0);
                        float2 f1v = __half22float2(*(__half2*)&p1);
                        lsum0 += f0v.x + f0v.y;
                        lsum1 += f1v.x + f1v.y;
                        pa[jj >> 1][(jj & 1) * 2 + 0] = p0;
                        pa[jj >> 1][(jj & 1) * 2 + 1] = p1;
                    }
                }

#pragma unroll
                for (int tt = 0; tt < 2; tt++) {
                    const int k0 = klocal + tt * 16;
#pragma unroll
                    for (int dp = 0; dp < 4; dp++) {
                        unsigned vb[4];
                        int vrow = k0 + ((lane & 8) ? 8 : 0) + (lane & 7);
                        int vcol = dp * 16 + ((lane & 16) ? 8 : 0);
                        ldsm4t(vb, sptr(&Vs[vrow * AP + vcol]));
                        mma16816(oacc[2 * dp], pa[tt], vb);
                        mma16816(oacc[2 * dp + 1], pa[tt], vb + 2);
                    }
                }
            }
            __syncthreads();
        }

        float l0 = lsum0 + __shfl_xor_sync(0xffffffffu, lsum0, 1);
        l0 += __shfl_xor_sync(0xffffffffu, l0, 2);
        float l1 = lsum1 + __shfl_xor_sync(0xffffffffu, lsum1, 1);
        l1 += __shfl_xor_sync(0xffffffffu, l1, 2);
        const float inv0 = 1.0f / l0;
        const float inv1 = 1.0f / l1;

        float* o0 = out + base + (size_t)rq0 * E_;
        float* o1 = out + base + (size_t)(rq0 + 8) * E_;
#pragma unroll
        for (int j = 0; j < 8; j++) {
            float2 v0 = make_float2(oacc[j][0] * inv0, oacc[j][1] * inv0);
            float2 v1 = make_float2(oacc[j][2] * inv1, oacc[j][3] * inv1);
            *(float2*)(o0 + j * 8 + col0) = v0;
            *(float2*)(o1 + j * 8 + col0) = v1;
        }
    }
}

// ---------------------------------------------------------------------------
extern "C" void kernel_launch(void* const* d_in, const int* in_sizes, int n_in,
                              void* d_out, int out_size) {
    const float* hs = (const float*)d_in[0];
    const int*   am = (const int*)d_in[1];
    const float* qw = (const float*)d_in[2];
    const float* qb = (const float*)d_in[3];
    const float* kw = (const float*)d_in[4];
    const float* kb = (const float*)d_in[5];
    const float* vw = (const float*)d_in[6];
    const float* vb = (const float*)d_in[7];
    float* out = (float*)d_out;

    cvt_x<<<(NTOK * (KAUG / 8) + 255) / 256, 256>>>(hs);
    dim3 gw((E_ * (KAUG / 8) + 255) / 256, 3);
    cvt_w<<<gw, 256>>>(qw, qb, kw, kb, vw, vb);

    cudaFuncSetAttribute(gemm_qkv, cudaFuncAttributeMaxDynamicSharedMemorySize, GEMM_SMEM);
    gemm_qkv<<<NPERSIST, 256, GEMM_SMEM>>>();

    cudaFuncSetAttribute(attn_mma, cudaFuncAttributeMaxDynamicSharedMemorySize, ATTN_SMEM);
    attn_mma<<<NPERSIST, 256, ATTN_SMEM>>>(am, out);
}

// round 14
// speedup vs baseline: 1.0841x; 1.0841x over previous
#include <cuda_runtime.h>
#include <cuda_fp16.h>
#include <cstdint>

#define B_ 2
#define S_ 4096
#define E_ 1024
#define H_ 16
#define D_ 64
#define NTOK (B_*S_)
#define NELEM (NTOK*E_)
#define LOG2E 1.4426950408889634f

__device__ __half g_q[NELEM];
__device__ __half g_k[NELEM];
__device__ __half g_v[NELEM];
__device__ __half g_xh[NELEM];            // fp16 X
__device__ __half g_wh[3 * E_ * E_];      // fp16 W (scaled)
__device__ float  g_bias[3 * E_];         // fp32 scaled bias

__device__ __forceinline__ void cp16(unsigned int dst, const void* src) {
    asm volatile("cp.async.cg.shared.global [%0], [%1], 16;" :: "r"(dst), "l"(src));
}
__device__ __forceinline__ unsigned int sptr(const void* p) {
    return (unsigned int)__cvta_generic_to_shared(p);
}
__device__ __forceinline__ unsigned hexp2pk(float a, float b) {
    __half2 hv = __floats2half2_rn(a, b);
    unsigned r;
    asm("ex2.approx.f16x2 %0, %1;" : "=r"(r) : "r"(*(unsigned*)&hv));
    return r;
}
__device__ __forceinline__ void mma16816(float* d, const unsigned* a, const unsigned* b) {
    asm volatile("mma.sync.aligned.m16n8k16.row.col.f32.f16.f16.f32 "
                 "{%0,%1,%2,%3}, {%4,%5,%6,%7}, {%8,%9}, {%0,%1,%2,%3};"
                 : "+f"(d[0]), "+f"(d[1]), "+f"(d[2]), "+f"(d[3])
                 : "r"(a[0]), "r"(a[1]), "r"(a[2]), "r"(a[3]), "r"(b[0]), "r"(b[1]));
}
__device__ __forceinline__ void ldsm4(unsigned* r, unsigned addr) {
    asm volatile("ldmatrix.sync.aligned.m8n8.x4.shared.b16 {%0,%1,%2,%3}, [%4];"
                 : "=r"(r[0]), "=r"(r[1]), "=r"(r[2]), "=r"(r[3]) : "r"(addr));
}
__device__ __forceinline__ void ldsm4t(unsigned* r, unsigned addr) {
    asm volatile("ldmatrix.sync.aligned.m8n8.x4.trans.shared.b16 {%0,%1,%2,%3}, [%4];"
                 : "=r"(r[0]), "=r"(r[1]), "=r"(r[2]), "=r"(r[3]) : "r"(addr));
}

// ---------------------------------------------------------------------------
// One-time conversions fp32 -> fp16 (8 elems / thread).
// ---------------------------------------------------------------------------
__global__ void __launch_bounds__(256) cvt_x(const float* __restrict__ X) {
    int idx8 = blockIdx.x * 256 + threadIdx.x;
    if (idx8 >= NELEM / 8) return;
    const float4* src = (const float4*)(X + (size_t)idx8 * 8);
    float4 v0 = src[0], v1 = src[1];
    __half2 h[4];
    h[0] = __floats2half2_rn(v0.x, v0.y);
    h[1] = __floats2half2_rn(v0.z, v0.w);
    h[2] = __floats2half2_rn(v1.x, v1.y);
    h[3] = __floats2half2_rn(v1.z, v1.w);
    *(uint4*)(g_xh + (size_t)idx8 * 8) = *(uint4*)h;
}

__global__ void __launch_bounds__(256) cvt_w(const float* __restrict__ qw, const float* __restrict__ qb,
                                             const float* __restrict__ kw, const float* __restrict__ kb,
                                             const float* __restrict__ vw, const float* __restrict__ vb) {
    const int which = blockIdx.y;
    const float* w = (which == 0) ? qw : ((which == 1) ? kw : vw);
    const float* b = (which == 0) ? qb : ((which == 1) ? kb : vb);
    const float scale = (which == 0) ? 0.125f * LOG2E : 1.0f;   // log2e folded into Q

    int idx8 = blockIdx.x * 256 + threadIdx.x;
    if (idx8 >= E_ * E_ / 8) return;
    int n = idx8 >> 7;              // row (output feature)
    int c = (idx8 & 127) * 8;
    const float4* src = (const float4*)(w + (size_t)n * E_ + c);
    float4 v0 = src[0], v1 = src[1];
    __half2 h[4];
    h[0] = __floats2half2_rn(v0.x * scale, v0.y * scale);
    h[1] = __floats2half2_rn(v0.z * scale, v0.w * scale);
    h[2] = __floats2half2_rn(v1.x * scale, v1.y * scale);
    h[3] = __floats2half2_rn(v1.z * scale, v1.w * scale);
    *(uint4*)(g_wh + (size_t)which * E_ * E_ + (size_t)n * E_ + c) = *(uint4*)h;
    if (c == 0) g_bias[which * E_ + n] = b[n] * scale;
}

// ---------------------------------------------------------------------------
// Projection GEMM v5: raw mma.16816 + ldmatrix. BM=128, BN=128, BK=64,
// 16 K-tiles, 3-stage cp.async ring with ONE syncthreads per tile,
// 8 warps of 64x32, bias added in epilogue. 2 blocks/SM.
// ---------------------------------------------------------------------------
#define GAP2 72
#define GSTG (128 * GAP2 * 2)               // 18432 B per matrix per stage
#define GEMM_SMEM (6 * GSTG)                // 3 stages x (A+B) = 110592 B

__global__ void __launch_bounds__(256, 2) gemm_qkv() {
    extern __shared__ char smg[];

    const int which = blockIdx.z;
    const __half* wbase = g_wh + (size_t)which * E_ * E_;
    const float* bbase = g_bias + which * E_;
    __half* C = (which == 0) ? g_q : ((which == 1) ? g_k : g_v);

    const int m0 = blockIdx.y * 128;
    const int n0 = blockIdx.x * 128;
    const int tid = threadIdx.x;
    const int warp = tid >> 5;
    const int lane = tid & 31;
    const int wm = warp >> 2;
    const int wn = warp & 3;

    float acc[4][4][4];
#pragma unroll
    for (int mi = 0; mi < 4; mi++)
#pragma unroll
        for (int nj = 0; nj < 4; nj++)
#pragma unroll
            for (int e = 0; e < 4; e++) acc[mi][nj][e] = 0.f;

    auto issue = [&](int kt) {
        const int s = kt % 3;
        __half* Ad = (__half*)(smg + s * GSTG);
        __half* Bd = (__half*)(smg + 3 * GSTG + s * GSTG);
#pragma unroll
        for (int i = 0; i < 4; i++) {
            int c = tid + i * 256;
            int row = c >> 3, kc = (c & 7) * 8;
            cp16(sptr(&Ad[row * GAP2 + kc]), g_xh + (size_t)(m0 + row) * E_ + kt * 64 + kc);
            cp16(sptr(&Bd[row * GAP2 + kc]), wbase + (size_t)(n0 + row) * E_ + kt * 64 + kc);
        }
        asm volatile("cp.async.commit_group;" ::);
    };

    const int arbase = wm * 64 + (lane & 7) + ((lane & 8) ? 8 : 0);
    const int acolb = (lane & 16) ? 8 : 0;
    const int brbase = wn * 32 + ((lane & 16) ? 8 : 0) + (lane & 7);
    const int bcolb = (lane & 8) ? 8 : 0;

    issue(0);
    issue(1);
    for (int kt = 0; kt < 16; kt++) {
        if (kt + 1 < 16) { asm volatile("cp.async.wait_group 1;" ::); }
        else             { asm volatile("cp.async.wait_group 0;" ::); }
        __syncthreads();
        if (kt + 2 < 16) issue(kt + 2);

        const int s = kt % 3;
        const __half* As = (const __half*)(smg + s * GSTG);
        const __half* Bsm = (const __half*)(smg + 3 * GSTG + s * GSTG);

#pragma unroll
        for (int tt = 0; tt < 4; tt++) {
            unsigned af[4][4];
#pragma unroll
            for (int mi = 0; mi < 4; mi++)
                ldsm4(af[mi], sptr(&As[(arbase + mi * 16) * GAP2 + tt * 16 + acolb]));
            unsigned bf[2][4];
#pragma unroll
            for (int p = 0; p < 2; p++)
                ldsm4(bf[p], sptr(&Bsm[(brbase + p * 16) * GAP2 + tt * 16 + bcolb]));
#pragma unroll
            for (int mi = 0; mi < 4; mi++) {
#pragma unroll
                for (int p = 0; p < 2; p++) {
                    mma16816(acc[mi][2 * p],     af[mi], bf[p]);
                    mma16816(acc[mi][2 * p + 1], af[mi], bf[p] + 2);
                }
            }
        }
    }

    // Epilogue: add bias, emit half2 directly from accumulator fragments.
    const int r0 = lane >> 2;
    const int c0 = (lane & 3) * 2;
    float2 bv[4];
#pragma unroll
    for (int nj = 0; nj < 4; nj++) {
        const int col = n0 + wn * 32 + nj * 8 + c0;
        bv[nj] = *(const float2*)(bbase + col);
    }
#pragma unroll
    for (int mi = 0; mi < 4; mi++) {
        const int row0 = m0 + wm * 64 + mi * 16 + r0;
#pragma unroll
        for (int nj = 0; nj < 4; nj++) {
            const int col = n0 + wn * 32 + nj * 8 + c0;
            __half2 h0 = __floats2half2_rn(acc[mi][nj][0] + bv[nj].x, acc[mi][nj][1] + bv[nj].y);
            __half2 h1 = __floats2half2_rn(acc[mi][nj][2] + bv[nj].x, acc[mi][nj][3] + bv[nj].y);
            *(__half2*)(C + (size_t)row0 * 1024 + col) = h0;
            *(__half2*)(C + (size_t)(row0 + 8) * 1024 + col) = h1;
        }
    }
}

// ---------------------------------------------------------------------------
// Banded attention v2: 64-query blocks, 4 warps (halved K/V ldsm redundancy),
// raw mma + ldmatrix, register softmax (log2 domain, ex2.approx.f16x2),
// double-buffered K/V, all-in-band fast path. 4 blocks/SM.
// Band = 9 key tiles of 64 covering [chunk0-256, chunk0+64+256).
// ---------------------------------------------------------------------------
#define AP 72
#define QS_OFF 0
#define KS_OFF (64*AP*2)
#define VS_OFF (KS_OFF + 2*64*AP*2)
#define FML_OFF (VS_OFF + 2*64*AP*2)
#define ATTN_SMEM (FML_OFF + 2*64*4)

__global__ void __launch_bounds__(128, 4) attn_mma(const int* __restrict__ am,
                                                   float* __restrict__ out) {
    extern __shared__ char smb[];
    __half* Qs = (__half*)(smb + QS_OFF);
    float* fml = (float*)(smb + FML_OFF);

    const int chunk0 = blockIdx.x * 64;
    const int h = blockIdx.y;
    const int b = blockIdx.z;
    const int tid = threadIdx.x;
    const int lane = tid & 31;
    const int warp = tid >> 5;          // 0..3
    const int q0 = warp * 16;
    const int col0 = (lane & 3) * 2;
    const size_t base = (size_t)b * S_ * E_ + h * 64;

    // Stage Q tile (64 rows) to shared
#pragma unroll
    for (int r = 0; r < 4; r++) {
        int c = tid + r * 128;
        int row = c >> 3, off = (c & 7) * 8;
        *(uint4*)(&Qs[row * AP + off]) =
            *(const uint4*)(g_q + base + (size_t)(chunk0 + row) * E_ + off);
    }

    const int kt_start = (chunk0 >= 256) ? 0 : ((256 - chunk0) / 64);
    const int kt_end = min(9, (S_ + 192 - chunk0) / 64 + 1);

    auto issueKV = [&](int kt, int s) {
        const int kglob = chunk0 - 256 + kt * 64;
        __half* Kd = (__half*)(smb + KS_OFF + s * (64 * AP * 2));
        __half* Vd = (__half*)(smb + VS_OFF + s * (64 * AP * 2));
#pragma unroll
        for (int i = 0; i < 4; i++) {
            int c = tid + i * 128;
            int row = c >> 3, off = (c & 7) * 8;
            size_t g = base + (size_t)(kglob + row) * E_ + off;
            cp16(sptr(&Kd[row * AP + off]), g_k + g);
            cp16(sptr(&Vd[row * AP + off]), g_v + g);
        }
        asm volatile("cp.async.commit_group;" ::);
        if (tid < 64)
            fml[s * 64 + tid] =
                (am[(size_t)b * S_ + kglob + tid] != 0) ? (-10000.f * LOG2E) : 0.f;
    };

    issueKV(kt_start, 0);
    __syncthreads();   // Qs + stage0 fml visible

    unsigned qa[4][4];
    {
        int qrow = q0 + (lane & 7) + ((lane & 8) ? 8 : 0);
        int qc = (lane & 16) ? 8 : 0;
#pragma unroll
        for (int t = 0; t < 4; t++)
            ldsm4(qa[t], sptr(&Qs[qrow * AP + t * 16 + qc]));
    }

    float oacc[8][4];
#pragma unroll
    for (int j = 0; j < 8; j++)
#pragma unroll
        for (int e = 0; e < 4; e++) oacc[j][e] = 0.f;
    float lsum0 = 0.f, lsum1 = 0.f;
    const int rq0 = chunk0 + q0 + (lane >> 2);

    for (int kt = kt_start; kt < kt_end; kt++) {
        const int s = (kt - kt_start) & 1;
        const int kglob = chunk0 - 256 + kt * 64;
        if (kt + 1 < kt_end) {
            issueKV(kt + 1, s ^ 1);
            asm volatile("cp.async.wait_group 1;" ::);
        } else {
            asm volatile("cp.async.wait_group 0;" ::);
        }
        __syncthreads();
        const __half* Ks = (const __half*)(smb + KS_OFF + s * (64 * AP * 2));
        const __half* Vs = (const __half*)(smb + VS_OFF + s * (64 * AP * 2));
        const float* fm = fml + s * 64;

#pragma unroll
        for (int sub = 0; sub < 2; sub++) {
            const int klocal = sub * 32;
            const int d0 = kglob + klocal - (chunk0 + q0);   // key0 - qrow_base
            if (d0 > 256 + 15 || d0 + 31 < -256) continue;    // fully out of band

            // S = Q K^T (K: non-trans ldmatrix)
            float sacc[4][4];
#pragma unroll
            for (int j = 0; j < 4; j++)
#pragma unroll
                for (int e = 0; e < 4; e++) sacc[j][e] = 0.f;
#pragma unroll
            for (int t = 0; t < 4; t++) {
#pragma unroll
                for (int p = 0; p < 2; p++) {
                    unsigned kb[4];
                    int krow = klocal + p * 16 + ((lane & 16) ? 8 : 0) + (lane & 7);
                    int kcol = t * 16 + ((lane & 8) ? 8 : 0);
                    ldsm4(kb, sptr(&Ks[krow * AP + kcol]));
                    mma16816(sacc[2 * p], qa[t], kb);
                    mma16816(sacc[2 * p + 1], qa[t], kb + 2);
                }
            }

            unsigned pa[2][4];
            if (d0 >= -241 && d0 <= 225) {
                // fast path: whole warp subtile in band
#pragma unroll
                for (int jj = 0; jj < 4; jj++) {
                    const float f0 = fm[klocal + jj * 8 + col0];
                    const float f1 = fm[klocal + jj * 8 + col0 + 1];
                    unsigned p0 = hexp2pk(sacc[jj][0] + f0, sacc[jj][1] + f1);
                    unsigned p1 = hexp2pk(sacc[jj][2] + f0, sacc[jj][3] + f1);
                    float2 f0v = __half22float2(*(__half2*)&p0);
                    float2 f1v = __half22float2(*(__half2*)&p1);
                    lsum0 += f0v.x + f0v.y;
                    lsum1 += f1v.x + f1v.y;
                    pa[jj >> 1][(jj & 1) * 2 + 0] = p0;
                    pa[jj >> 1][(jj & 1) * 2 + 1] = p1;
                }
            } else {
#pragma unroll
                for (int jj = 0; jj < 4; jj++) {
                    const int keyg = kglob + klocal + jj * 8 + col0;
                    const float f0 = fm[klocal + jj * 8 + col0];
                    const float f1 = fm[klocal + jj * 8 + col0 + 1];
                    const int r00 = keyg - rq0;
                    const float t00 = (r00 >= -256 && r00 <= 256) ? sacc[jj][0] + f0 : -1e5f;
                    const float t01 = (r00 + 1 >= -256 && r00 + 1 <= 256) ? sacc[jj][1] + f1 : -1e5f;
                    const float t10 = (r00 - 8 >= -256 && r00 - 8 <= 256) ? sacc[jj][2] + f0 : -1e5f;
                    const float t11 = (r00 - 7 >= -256 && r00 - 7 <= 256) ? sacc[jj][3] + f1 : -1e5f;
                    unsigned p0 = hexp2pk(t00, t01);
                    unsigned p1 = hexp2pk(t10, t11);
                    float2 f0v = __half22float2(*(__half2*)&p0);
                    float2 f1v = __half22float2(*(__half2*)&p1);
                    lsum0 += f0v.x + f0v.y;
                    lsum1 += f1v.x + f1v.y;
                    pa[jj >> 1][(jj & 1) * 2 + 0] = p0;
                    pa[jj >> 1][(jj & 1) * 2 + 1] = p1;
                }
            }

            // O += P V (V: trans ldmatrix)
#pragma unroll
            for (int tt = 0; tt < 2; tt++) {
                const int k0 = klocal + tt * 16;
#pragma unroll
                for (int dp = 0; dp < 4; dp++) {
                    unsigned vb[4];
                    int vrow = k0 + ((lane & 8) ? 8 : 0) + (lane & 7);
                    int vcol = dp * 16 + ((lane & 16) ? 8 : 0);
                    ldsm4t(vb, sptr(&Vs[vrow * AP + vcol]));
                    mma16816(oacc[2 * dp], pa[tt], vb);
                    mma16816(oacc[2 * dp + 1], pa[tt], vb + 2);
                }
            }
        }
        __syncthreads();
    }

    float l0 = lsum0 + __shfl_xor_sync(0xffffffffu, lsum0, 1);
    l0 += __shfl_xor_sync(0xffffffffu, l0, 2);
    float l1 = lsum1 + __shfl_xor_sync(0xffffffffu, lsum1, 1);
    l1 += __shfl_xor_sync(0xffffffffu, l1, 2);
    const float inv0 = 1.0f / l0;
    const float inv1 = 1.0f / l1;

    float* o0 = out + base + (size_t)rq0 * E_;
    float* o1 = out + base + (size_t)(rq0 + 8) * E_;
#pragma unroll
    for (int j = 0; j < 8; j++) {
        float2 v0 = make_float2(oacc[j][0] * inv0, oacc[j][1] * inv0);
        float2 v1 = make_float2(oacc[j][2] * inv1, oacc[j][3] * inv1);
        *(float2*)(o0 + j * 8 + col0) = v0;
        *(float2*)(o1 + j * 8 + col0) = v1;
    }
}

// ---------------------------------------------------------------------------
extern "C" void kernel_launch(void* const* d_in, const int* in_sizes, int n_in,
                              void* d_out, int out_size) {
    const float* hs = (const float*)d_in[0];
    const int*   am = (const int*)d_in[1];
    const float* qw = (const float*)d_in[2];
    const float* qb = (const float*)d_in[3];
    const float* kw = (const float*)d_in[4];
    const float* kb = (const float*)d_in[5];
    const float* vw = (const float*)d_in[6];
    const float* vb = (const float*)d_in[7];
    float* out = (float*)d_out;

    cvt_x<<<(NELEM / 8 + 255) / 256, 256>>>(hs);
    dim3 gw((E_ * E_ / 8 + 255) / 256, 3);
    cvt_w<<<gw, 256>>>(qw, qb, kw, kb, vw, vb);

    cudaFuncSetAttribute(gemm_qkv, cudaFuncAttributeMaxDynamicSharedMemorySize, GEMM_SMEM);
    dim3 gg(E_ / 128, NTOK / 128, 3);
    gemm_qkv<<<gg, 256, GEMM_SMEM>>>();

    cudaFuncSetAttribute(attn_mma, cudaFuncAttributeMaxDynamicSharedMemorySize, ATTN_SMEM);
    dim3 ga(S_ / 64, H_, B_);
    attn_mma<<<ga, 128, ATTN_SMEM>>>(am, out);
}

// round 16
// speedup vs baseline: 1.1033x; 1.0176x over previous
#include <cuda_runtime.h>
#include <cuda_fp16.h>
#include <cstdint>

#define B_ 2
#define S_ 4096
#define E_ 1024
#define H_ 16
#define D_ 64
#define NTOK (B_*S_)
#define NELEM (NTOK*E_)
#define LOG2E 1.4426950408889634f

__device__ __half g_q[NELEM];
__device__ __half g_k[NELEM];
__device__ __half g_v[NELEM];
__device__ __half g_xh[NELEM];            // fp16 X
__device__ __half g_wh[3 * E_ * E_];      // fp16 W (scaled)
__device__ float  g_bias[3 * E_];         // fp32 scaled bias

__device__ __forceinline__ void cp16(unsigned int dst, const void* src) {
    asm volatile("cp.async.cg.shared.global [%0], [%1], 16;" :: "r"(dst), "l"(src));
}
__device__ __forceinline__ unsigned int sptr(const void* p) {
    return (unsigned int)__cvta_generic_to_shared(p);
}
__device__ __forceinline__ unsigned hexp2pk(float a, float b) {
    __half2 hv = __floats2half2_rn(a, b);
    unsigned r;
    asm("ex2.approx.f16x2 %0, %1;" : "=r"(r) : "r"(*(unsigned*)&hv));
    return r;
}
__device__ __forceinline__ void mma16816(float* d, const unsigned* a, const unsigned* b) {
    asm volatile("mma.sync.aligned.m16n8k16.row.col.f32.f16.f16.f32 "
                 "{%0,%1,%2,%3}, {%4,%5,%6,%7}, {%8,%9}, {%0,%1,%2,%3};"
                 : "+f"(d[0]), "+f"(d[1]), "+f"(d[2]), "+f"(d[3])
                 : "r"(a[0]), "r"(a[1]), "r"(a[2]), "r"(a[3]), "r"(b[0]), "r"(b[1]));
}
__device__ __forceinline__ void ldsm4(unsigned* r, unsigned addr) {
    asm volatile("ldmatrix.sync.aligned.m8n8.x4.shared.b16 {%0,%1,%2,%3}, [%4];"
                 : "=r"(r[0]), "=r"(r[1]), "=r"(r[2]), "=r"(r[3]) : "r"(addr));
}
__device__ __forceinline__ void ldsm4t(unsigned* r, unsigned addr) {
    asm volatile("ldmatrix.sync.aligned.m8n8.x4.trans.shared.b16 {%0,%1,%2,%3}, [%4];"
                 : "=r"(r[0]), "=r"(r[1]), "=r"(r[2]), "=r"(r[3]) : "r"(addr));
}

// ---------------------------------------------------------------------------
// Single fused conversion kernel: blocks [0,4096) convert X, rest convert W.
// ---------------------------------------------------------------------------
#define XBLKS (NELEM / 8 / 256)          // 4096
#define WBLKS (E_ * E_ / 8 / 256)        // 512

__global__ void __launch_bounds__(256) cvt_all(const float* __restrict__ X,
                                               const float* __restrict__ qw, const float* __restrict__ qb,
                                               const float* __restrict__ kw, const float* __restrict__ kb,
                                               const float* __restrict__ vw, const float* __restrict__ vb) {
    const int bid = blockIdx.x;
    if (bid < XBLKS) {
        int idx8 = bid * 256 + threadIdx.x;
        const float4* src = (const float4*)(X + (size_t)idx8 * 8);
        float4 v0 = src[0], v1 = src[1];
        __half2 h[4];
        h[0] = __floats2half2_rn(v0.x, v0.y);
        h[1] = __floats2half2_rn(v0.z, v0.w);
        h[2] = __floats2half2_rn(v1.x, v1.y);
        h[3] = __floats2half2_rn(v1.z, v1.w);
        *(uint4*)(g_xh + (size_t)idx8 * 8) = *(uint4*)h;
    } else {
        const int r = bid - XBLKS;
        const int which = r >> 9;               // 0..2
        const int idx8 = (r & 511) * 256 + threadIdx.x;
        const float* w = (which == 0) ? qw : ((which == 1) ? kw : vw);
        const float* b = (which == 0) ? qb : ((which == 1) ? kb : vb);
        const float scale = (which == 0) ? 0.125f * LOG2E : 1.0f;
        int n = idx8 >> 7;
        int c = (idx8 & 127) * 8;
        const float4* src = (const float4*)(w + (size_t)n * E_ + c);
        float4 v0 = src[0], v1 = src[1];
        __half2 h[4];
        h[0] = __floats2half2_rn(v0.x * scale, v0.y * scale);
        h[1] = __floats2half2_rn(v0.z * scale, v0.w * scale);
        h[2] = __floats2half2_rn(v1.x * scale, v1.y * scale);
        h[3] = __floats2half2_rn(v1.z * scale, v1.w * scale);
        *(uint4*)(g_wh + (size_t)which * E_ * E_ + (size_t)n * E_ + c) = *(uint4*)h;
        if (c == 0) g_bias[which * E_ + n] = b[n] * scale;
    }
}

// ---------------------------------------------------------------------------
// Projection GEMM v5 (unchanged): raw mma.16816 + ldmatrix. BM=BN=128, BK=64,
// 3-stage cp.async ring, one syncthreads per tile, bias in epilogue. 2/SM.
// ---------------------------------------------------------------------------
#define GAP2 72
#define GSTG (128 * GAP2 * 2)
#define GEMM_SMEM (6 * GSTG)

__global__ void __launch_bounds__(256, 2) gemm_qkv() {
    extern __shared__ char smg[];

    const int which = blockIdx.z;
    const __half* wbase = g_wh + (size_t)which * E_ * E_;
    const float* bbase = g_bias + which * E_;
    __half* C = (which == 0) ? g_q : ((which == 1) ? g_k : g_v);

    const int m0 = blockIdx.y * 128;
    const int n0 = blockIdx.x * 128;
    const int tid = threadIdx.x;
    const int warp = tid >> 5;
    const int lane = tid & 31;
    const int wm = warp >> 2;
    const int wn = warp & 3;

    float acc[4][4][4];
#pragma unroll
    for (int mi = 0; mi < 4; mi++)
#pragma unroll
        for (int nj = 0; nj < 4; nj++)
#pragma unroll
            for (int e = 0; e < 4; e++) acc[mi][nj][e] = 0.f;

    auto issue = [&](int kt) {
        const int s = kt % 3;
        __half* Ad = (__half*)(smg + s * GSTG);
        __half* Bd = (__half*)(smg + 3 * GSTG + s * GSTG);
#pragma unroll
        for (int i = 0; i < 4; i++) {
            int c = tid + i * 256;
            int row = c >> 3, kc = (c & 7) * 8;
            cp16(sptr(&Ad[row * GAP2 + kc]), g_xh + (size_t)(m0 + row) * E_ + kt * 64 + kc);
            cp16(sptr(&Bd[row * GAP2 + kc]), wbase + (size_t)(n0 + row) * E_ + kt * 64 + kc);
        }
        asm volatile("cp.async.commit_group;" ::);
    };

    const int arbase = wm * 64 + (lane & 7) + ((lane & 8) ? 8 : 0);
    const int acolb = (lane & 16) ? 8 : 0;
    const int brbase = wn * 32 + ((lane & 16) ? 8 : 0) + (lane & 7);
    const int bcolb = (lane & 8) ? 8 : 0;

    issue(0);
    issue(1);
    for (int kt = 0; kt < 16; kt++) {
        if (kt + 1 < 16) { asm volatile("cp.async.wait_group 1;" ::); }
        else             { asm volatile("cp.async.wait_group 0;" ::); }
        __syncthreads();
        if (kt + 2 < 16) issue(kt + 2);

        const int s = kt % 3;
        const __half* As = (const __half*)(smg + s * GSTG);
        const __half* Bsm = (const __half*)(smg + 3 * GSTG + s * GSTG);

#pragma unroll
        for (int tt = 0; tt < 4; tt++) {
            unsigned af[4][4];
#pragma unroll
            for (int mi = 0; mi < 4; mi++)
                ldsm4(af[mi], sptr(&As[(arbase + mi * 16) * GAP2 + tt * 16 + acolb]));
            unsigned bf[2][4];
#pragma unroll
            for (int p = 0; p < 2; p++)
                ldsm4(bf[p], sptr(&Bsm[(brbase + p * 16) * GAP2 + tt * 16 + bcolb]));
#pragma unroll
            for (int mi = 0; mi < 4; mi++) {
#pragma unroll
                for (int p = 0; p < 2; p++) {
                    mma16816(acc[mi][2 * p],     af[mi], bf[p]);
                    mma16816(acc[mi][2 * p + 1], af[mi], bf[p] + 2);
                }
            }
        }
    }

    const int r0 = lane >> 2;
    const int c0 = (lane & 3) * 2;
    float2 bv[4];
#pragma unroll
    for (int nj = 0; nj < 4; nj++) {
        const int col = n0 + wn * 32 + nj * 8 + c0;
        bv[nj] = *(const float2*)(bbase + col);
    }
#pragma unroll
    for (int mi = 0; mi < 4; mi++) {
        const int row0 = m0 + wm * 64 + mi * 16 + r0;
#pragma unroll
        for (int nj = 0; nj < 4; nj++) {
            const int col = n0 + wn * 32 + nj * 8 + c0;
            __half2 h0 = __floats2half2_rn(acc[mi][nj][0] + bv[nj].x, acc[mi][nj][1] + bv[nj].y);
            __half2 h1 = __floats2half2_rn(acc[mi][nj][2] + bv[nj].x, acc[mi][nj][3] + bv[nj].y);
            *(__half2*)(C + (size_t)row0 * 1024 + col) = h0;
            *(__half2*)(C + (size_t)(row0 + 8) * 1024 + col) = h1;
        }
    }
}

// ---------------------------------------------------------------------------
// Banded attention v3: 64-query blocks, 4 warps, double-buffered K/V,
// register softmax (log2 domain, ex2.approx.f16x2), all-in-band fast path,
// and per-stage mask-zero flag that skips additive-mask work entirely.
// ---------------------------------------------------------------------------
#define AP 72
#define QS_OFF 0
#define KS_OFF (64*AP*2)
#define VS_OFF (KS_OFF + 2*64*AP*2)
#define FML_OFF (VS_OFF + 2*64*AP*2)
#define MFLAG_OFF (FML_OFF + 2*64*4)
#define ATTN_SMEM (MFLAG_OFF + 4*4)

__global__ void __launch_bounds__(128, 4) attn_mma(const int* __restrict__ am,
                                                   float* __restrict__ out) {
    extern __shared__ char smb[];
    __half* Qs = (__half*)(smb + QS_OFF);
    float* fml = (float*)(smb + FML_OFF);
    unsigned* mflag = (unsigned*)(smb + MFLAG_OFF);   // [stage][warp<2]

    const int chunk0 = blockIdx.x * 64;
    const int h = blockIdx.y;
    const int b = blockIdx.z;
    const int tid = threadIdx.x;
    const int lane = tid & 31;
    const int warp = tid >> 5;
    const int q0 = warp * 16;
    const int col0 = (lane & 3) * 2;
    const size_t base = (size_t)b * S_ * E_ + h * 64;

#pragma unroll
    for (int r = 0; r < 4; r++) {
        int c = tid + r * 128;
        int row = c >> 3, off = (c & 7) * 8;
        *(uint4*)(&Qs[row * AP + off]) =
            *(const uint4*)(g_q + base + (size_t)(chunk0 + row) * E_ + off);
    }

    const int kt_start = (chunk0 >= 256) ? 0 : ((256 - chunk0) / 64);
    const int kt_end = min(9, (S_ + 192 - chunk0) / 64 + 1);

    auto issueKV = [&](int kt, int s) {
        const int kglob = chunk0 - 256 + kt * 64;
        __half* Kd = (__half*)(smb + KS_OFF + s * (64 * AP * 2));
        __half* Vd = (__half*)(smb + VS_OFF + s * (64 * AP * 2));
#pragma unroll
        for (int i = 0; i < 4; i++) {
            int c = tid + i * 128;
            int row = c >> 3, off = (c & 7) * 8;
            size_t g = base + (size_t)(kglob + row) * E_ + off;
            cp16(sptr(&Kd[row * AP + off]), g_k + g);
            cp16(sptr(&Vd[row * AP + off]), g_v + g);
        }
        asm volatile("cp.async.commit_group;" ::);
        if (warp < 2) {
            const bool nz = am[(size_t)b * S_ + kglob + tid] != 0;
            fml[s * 64 + tid] = nz ? (-10000.f * LOG2E) : 0.f;
            unsigned any = __ballot_sync(0xffffffffu, nz);
            if (lane == 0) mflag[s * 2 + warp] = any;
        }
    };

    issueKV(kt_start, 0);
    __syncthreads();

    unsigned qa[4][4];
    {
        int qrow = q0 + (lane & 7) + ((lane & 8) ? 8 : 0);
        int qc = (lane & 16) ? 8 : 0;
#pragma unroll
        for (int t = 0; t < 4; t++)
            ldsm4(qa[t], sptr(&Qs[qrow * AP + t * 16 + qc]));
    }

    float oacc[8][4];
#pragma unroll
    for (int j = 0; j < 8; j++)
#pragma unroll
        for (int e = 0; e < 4; e++) oacc[j][e] = 0.f;
    float lsum0 = 0.f, lsum1 = 0.f;
    const int rq0 = chunk0 + q0 + (lane >> 2);

    for (int kt = kt_start; kt < kt_end; kt++) {
        const int s = (kt - kt_start) & 1;
        const int kglob = chunk0 - 256 + kt * 64;
        if (kt + 1 < kt_end) {
            issueKV(kt + 1, s ^ 1);
            asm volatile("cp.async.wait_group 1;" ::);
        } else {
            asm volatile("cp.async.wait_group 0;" ::);
        }
        __syncthreads();
        const __half* Ks = (const __half*)(smb + KS_OFF + s * (64 * AP * 2));
        const __half* Vs = (const __half*)(smb + VS_OFF + s * (64 * AP * 2));
        const float* fm = fml + s * 64;
        const bool hasmask = (mflag[s * 2] | mflag[s * 2 + 1]) != 0u;

#pragma unroll
        for (int sub = 0; sub < 2; sub++) {
            const int klocal = sub * 32;
            const int d0 = kglob + klocal - (chunk0 + q0);
            if (d0 > 256 + 15 || d0 + 31 < -256) continue;

            float sacc[4][4];
#pragma unroll
            for (int j = 0; j < 4; j++)
#pragma unroll
                for (int e = 0; e < 4; e++) sacc[j][e] = 0.f;
#pragma unroll
            for (int t = 0; t < 4; t++) {
#pragma unroll
                for (int p = 0; p < 2; p++) {
                    unsigned kb[4];
                    int krow = klocal + p * 16 + ((lane & 16) ? 8 : 0) + (lane & 7);
                    int kcol = t * 16 + ((lane & 8) ? 8 : 0);
                    ldsm4(kb, sptr(&Ks[krow * AP + kcol]));
                    mma16816(sacc[2 * p], qa[t], kb);
                    mma16816(sacc[2 * p + 1], qa[t], kb + 2);
                }
            }

            unsigned pa[2][4];
            if (!hasmask && d0 >= -241 && d0 <= 225) {
                // fastest path: all in band, no mask contribution
#pragma unroll
                for (int jj = 0; jj < 4; jj++) {
                    unsigned p0 = hexp2pk(sacc[jj][0], sacc[jj][1]);
                    unsigned p1 = hexp2pk(sacc[jj][2], sacc[jj][3]);
                    float2 f0v = __half22float2(*(__half2*)&p0);
                    float2 f1v = __half22float2(*(__half2*)&p1);
                    lsum0 += f0v.x + f0v.y;
                    lsum1 += f1v.x + f1v.y;
                    pa[jj >> 1][(jj & 1) * 2 + 0] = p0;
                    pa[jj >> 1][(jj & 1) * 2 + 1] = p1;
                }
            } else if (d0 >= -241 && d0 <= 225) {
#pragma unroll
                for (int jj = 0; jj < 4; jj++) {
                    const float f0 = fm[klocal + jj * 8 + col0];
                    const float f1 = fm[klocal + jj * 8 + col0 + 1];
                    unsigned p0 = hexp2pk(sacc[jj][0] + f0, sacc[jj][1] + f1);
                    unsigned p1 = hexp2pk(sacc[jj][2] + f0, sacc[jj][3] + f1);
                    float2 f0v = __half22float2(*(__half2*)&p0);
                    float2 f1v = __half22float2(*(__half2*)&p1);
                    lsum0 += f0v.x + f0v.y;
                    lsum1 += f1v.x + f1v.y;
                    pa[jj >> 1][(jj & 1) * 2 + 0] = p0;
                    pa[jj >> 1][(jj & 1) * 2 + 1] = p1;
                }
            } else {
#pragma unroll
                for (int jj = 0; jj < 4; jj++) {
                    const int keyg = kglob + klocal + jj * 8 + col0;
                    const float f0 = fm[klocal + jj * 8 + col0];
                    const float f1 = fm[klocal + jj * 8 + col0 + 1];
                    const int r00 = keyg - rq0;
                    const float t00 = (r00 >= -256 && r00 <= 256) ? sacc[jj][0] + f0 : -1e5f;
                    const float t01 = (r00 + 1 >= -256 && r00 + 1 <= 256) ? sacc[jj][1] + f1 : -1e5f;
                    const float t10 = (r00 - 8 >= -256 && r00 - 8 <= 256) ? sacc[jj][2] + f0 : -1e5f;
                    const float t11 = (r00 - 7 >= -256 && r00 - 7 <= 256) ? sacc[jj][3] + f1 : -1e5f;
                    unsigned p0 = hexp2pk(t00, t01);
                    unsigned p1 = hexp2pk(t10, t11);
                    float2 f0v = __half22float2(*(__half2*)&p0);
                    float2 f1v = __half22float2(*(__half2*)&p1);
                    lsum0 += f0v.x + f0v.y;
                    lsum1 += f1v.x + f1v.y;
                    pa[jj >> 1][(jj & 1) * 2 + 0] = p0;
                    pa[jj >> 1][(jj & 1) * 2 + 1] = p1;
                }
            }

#pragma unroll
            for (int tt = 0; tt < 2; tt++) {
                const int k0 = klocal + tt * 16;
#pragma unroll
                for (int dp = 0; dp < 4; dp++) {
                    unsigned vb[4];
                    int vrow = k0 + ((lane & 8) ? 8 : 0) + (lane & 7);
                    int vcol = dp * 16 + ((lane & 16) ? 8 : 0);
                    ldsm4t(vb, sptr(&Vs[vrow * AP + vcol]));
                    mma16816(oacc[2 * dp], pa[tt], vb);
                    mma16816(oacc[2 * dp + 1], pa[tt], vb + 2);
                }
            }
        }
        __syncthreads();
    }

    float l0 = lsum0 + __shfl_xor_sync(0xffffffffu, lsum0, 1);
    l0 += __shfl_xor_sync(0xffffffffu, l0, 2);
    float l1 = lsum1 + __shfl_xor_sync(0xffffffffu, lsum1, 1);
    l1 += __shfl_xor_sync(0xffffffffu, l1, 2);
    const float inv0 = 1.0f / l0;
    const float inv1 = 1.0f / l1;

    float* o0 = out + base + (size_t)rq0 * E_;
    float* o1 = out + base + (size_t)(rq0 + 8) * E_;
#pragma unroll
    for (int j = 0; j < 8; j++) {
        float2 v0 = make_float2(oacc[j][0] * inv0, oacc[j][1] * inv0);
        float2 v1 = make_float2(oacc[j][2] * inv1, oacc[j][3] * inv1);
        *(float2*)(o0 + j * 8 + col0) = v0;
        *(float2*)(o1 + j * 8 + col0) = v1;
    }
}

// ---------------------------------------------------------------------------
extern "C" void kernel_launch(void* const* d_in, const int* in_sizes, int n_in,
                              void* d_out, int out_size) {
    const float* hs = (const float*)d_in[0];
    const int*   am = (const int*)d_in[1];
    const float* qw = (const float*)d_in[2];
    const float* qb = (const float*)d_in[3];
    const float* kw = (const float*)d_in[4];
    const float* kb = (const float*)d_in[5];
    const float* vw = (const float*)d_in[6];
    const float* vb = (const float*)d_in[7];
    float* out = (float*)d_out;

    cvt_all<<<XBLKS + 3 * WBLKS, 256>>>(hs, qw, qb, kw, kb, vw, vb);

    cudaFuncSetAttribute(gemm_qkv, cudaFuncAttributeMaxDynamicSharedMemorySize, GEMM_SMEM);
    dim3 gg(E_ / 128, NTOK / 128, 3);
    gemm_qkv<<<gg, 256, GEMM_SMEM>>>();

    cudaFuncSetAttribute(attn_mma, cudaFuncAttributeMaxDynamicSharedMemorySize, ATTN_SMEM);
    dim3 ga(S_ / 64, H_, B_);
    attn_mma<<<ga, 128, ATTN_SMEM>>>(am, out);
}